// round 17
// baseline (speedup 1.0000x reference)
#include <cuda_runtime.h>

#define B_TOTAL   1024
#define T_STEPS   512
#define NGATE     256
#define NCTA      148
#define NCTA7     136      /* 136 CTAs * 7 + 12 CTAs * 6 = 1024 */
#define NTHREADS  384
#define HSTRIDE   68

typedef unsigned long long u64;

__device__ __forceinline__ u64 ffma2(u64 a, u64 b, u64 c) {
    u64 d;
    asm("fma.rn.f32x2 %0, %1, %2, %3;" : "=l"(d) : "l"(a), "l"(b), "l"(c));
    return d;
}
__device__ __forceinline__ float hadd2(u64 v) {
    float lo, hi;
    asm("mov.b64 {%0, %1}, %2;" : "=f"(lo), "=f"(hi) : "l"(v));
    return lo + hi;
}
__device__ __forceinline__ u64 packf2(float lo, float hi) {
    u64 v;
    asm("mov.b64 %0, {%1, %2};" : "=l"(v) : "f"(lo), "f"(hi));
    return v;
}
__device__ __forceinline__ float tanh_apx(float x) {
    float y;
    asm("tanh.approx.f32 %0, %1;" : "=f"(y) : "f"(x));
    return y;
}
__device__ __forceinline__ float sig_apx(float x) {
    return fmaf(0.5f, tanh_apx(0.5f * x), 0.5f);
}

#define BAR_SYNC(id, cnt)   asm volatile("bar.sync %0, %1;"   :: "r"(id), "r"(cnt) : "memory")
#define BAR_ARRIVE(id, cnt) asm volatile("bar.arrive %0, %1;" :: "r"(id), "r"(cnt) : "memory")
// barrier ids: 0 = __syncthreads, 1/2 = FULL[slot], 3/4 = EMPTY[slot],
//              5 = alpha-internal (256), 6 = beta-internal (128)

// SMEM (bytes), sized for NB=7:
//  wq    [0, 196608): quads. A=whh0 [0,4096), B=wih1 [4096,8192), C=whh1 [8192,12288)
//        A/B sublayout: [rowhi][kc][half][row&127]   conflict-free
//        C   sublayout: [row>>6][kc][half][row&63]   conflict-free
//  g0    [196608): f32 [7 b][256 g]
//  g1a   [203776): f32 ring, 2 slots x [7 b][256 g]  (alpha partial, includes b1)
//  g1b   [218112): f32 [7 b][256 g]                  (beta partial)
//  h0    [225280): f32 [7 b][68]   half0 @ +0, half1 @ +36 floats
//  h1    [227200)
//  wfc   [229120): f32 [64]
#define SM_W      0
#define SM_G0     196608
#define SM_G1A    203776
#define SM_G1B    218112
#define SM_H0     225280
#define SM_H1     227200
#define SM_WFC    229120
#define SMEM_BYTES 229376
#define G1A_SLOT  1792     /* floats per ring slot */

template<int NBT>
__device__ __forceinline__ void lstm_body(
    int bbase, const float* __restrict__ x,
    const float* __restrict__ W_ih0,
    const float* __restrict__ b_ih0, const float* __restrict__ b_hh0,
    const float* __restrict__ b_ih1, const float* __restrict__ b_hh1,
    const float* __restrict__ b_fc, float* __restrict__ out,
    ulonglong2* wq, float* g0_s, float* g1a_s, float* g1b_s,
    float* h0_s, float* h1_s, float* wfc_s)
{
    const int tid  = threadIdx.x;
    const int lane = tid & 31;
    const int half = lane >> 4;
    const int hofs = half * 36;
    const int wid  = tid >> 5;

    for (int i = tid; i < NBT * HSTRIDE; i += NTHREADS) { h0_s[i] = 0.0f; h1_s[i] = 0.0f; }
    __syncthreads();   // weights + zeros visible to all

    if (tid < 256) {
        // ================= ALPHA: whh0 + wih1 on h0 ; act0 =================
        const int sl    = (wid & 7) * 16 + (lane & 15);
        const int wofsA = half * 128 + sl;
        const int myrow = sl + half * 128;
        // positional rowhi blocks: own = this lane's stored row, oth = partner's
        const int oOwn = half ? 2048 : 0;
        const int oOth = 2048 - oOwn;
        const float b0v = b_ih0[myrow] + b_hh0[myrow];
        const float b1v = b_ih1[myrow] + b_hh1[myrow];
        const u64 initA = packf2(b0v, 0.0f);   // bias folded into own-acc init
        const u64 initB = packf2(b1v, 0.0f);

        const int uA  = tid & 63;
        const int bA0 = tid >> 6;                 // 0..3
        const int bA1 = 4 + bA0;
        const bool hasA1 = (tid < (NBT - 4) * 64);
        const int pad = (uA >> 5) << 2;
        const int gi0 = bA0 * NGATE + uA, hs0 = bA0 * HSTRIDE + uA + pad;
        const int gi1 = bA1 * NGATE + uA, hs1 = bA1 * HSTRIDE + uA + pad;
        const float* xr0 = x + (size_t)(bbase + bA0) * T_STEPS;
        const float* xr1 = x + (size_t)(bbase + bA1) * T_STEPS;
        const float wxi = W_ih0[uA];
        const float wxf = W_ih0[64 + uA];
        const float wxg = W_ih0[128 + uA];
        const float wxo = W_ih0[192 + uA];
        float cA0 = 0.0f, cA1 = 0.0f;

        auto actL0 = [&](int gi, int hs, float& c, float xv) {
            float q0 = fmaf(wxi, xv, g0_s[gi]);
            float q1 = fmaf(wxf, xv, g0_s[gi + 64]);
            float q2 = fmaf(wxg, xv, g0_s[gi + 128]);
            float q3 = fmaf(wxo, xv, g0_s[gi + 192]);
            float ii = sig_apx(q0), ff = sig_apx(q1), gv = tanh_apx(q2), oo = sig_apx(q3);
            c = ff * c + ii * gv;
            h0_s[hs] = oo * tanh_apx(c);
        };

        // prologue: g0(0) = b0 ; act0(0)
#pragma unroll
        for (int b = 0; b < NBT; b++) g0_s[b * NGATE + myrow] = b0v;
        BAR_SYNC(5, 256);
        actL0(gi0, hs0, cA0, __ldg(xr0));
        if (hasA1) actL0(gi1, hs1, cA1, __ldg(xr1));
        BAR_SYNC(5, 256);

        for (int t = 0; t < T_STEPS; t++) {
            if (t >= 2) BAR_SYNC(3 + (t & 1), 384);      // EMPTY: slot reusable
            float* g1a = g1a_s + (t & 1) * G1A_SLOT;

            u64 aAown[NBT], aAoth[NBT], aBown[NBT], aBoth[NBT];
#pragma unroll
            for (int b = 0; b < NBT; b++) { aAown[b]=initA; aAoth[b]=0ull; aBown[b]=initB; aBoth[b]=0ull; }
#pragma unroll
            for (int kc = 0; kc < 8; kc++) {
                ulonglong2 waOwn = wq[oOwn        + kc * 256 + wofsA];
                ulonglong2 waOth = wq[oOth        + kc * 256 + wofsA];
                ulonglong2 wbOwn = wq[4096 + oOwn + kc * 256 + wofsA];
                ulonglong2 wbOth = wq[4096 + oOth + kc * 256 + wofsA];
#pragma unroll
                for (int b = 0; b < NBT; b++) {
                    ulonglong2 h2 = *(const ulonglong2*)(h0_s + b * HSTRIDE + hofs + kc * 4);
                    aAown[b] = ffma2(waOwn.x, h2.x, aAown[b]); aAown[b] = ffma2(waOwn.y, h2.y, aAown[b]);
                    aAoth[b] = ffma2(waOth.x, h2.x, aAoth[b]); aAoth[b] = ffma2(waOth.y, h2.y, aAoth[b]);
                    aBown[b] = ffma2(wbOwn.x, h2.x, aBown[b]); aBown[b] = ffma2(wbOwn.y, h2.y, aBown[b]);
                    aBoth[b] = ffma2(wbOth.x, h2.x, aBoth[b]); aBoth[b] = ffma2(wbOth.y, h2.y, aBoth[b]);
                }
            }
            // branchless single-shfl cross-half reduction (bias pre-folded)
#pragma unroll
            for (int b = 0; b < NBT; b++) {
                float sendA = hadd2(aAoth[b]);
                float sendB = hadd2(aBoth[b]);
                float recvA = __shfl_xor_sync(0xffffffffu, sendA, 16);
                float recvB = __shfl_xor_sync(0xffffffffu, sendB, 16);
                g0_s[b * NGATE + myrow] = hadd2(aAown[b]) + recvA;   // g0(t+1)
                g1a [b * NGATE + myrow] = hadd2(aBown[b]) + recvB;   // g1a(t)
            }
            BAR_SYNC(5, 256);                 // drain stores (alpha-wide)
            BAR_ARRIVE(1 + (t & 1), 384);     // FULL: g1a(t) published to beta

            if (t < T_STEPS - 1) {            // act0(t+1)
                float xv0 = __ldg(xr0 + t + 1);
                actL0(gi0, hs0, cA0, xv0);
                if (hasA1) {
                    float xv1 = __ldg(xr1 + t + 1);
                    actL0(gi1, hs1, cA1, xv1);
                }
            }
            BAR_SYNC(5, 256);                 // h0(t+1) visible for next mv
        }
    } else {
        // ================= BETA: whh1 on h1 ; act1 =================
        const int sb    = (wid - 8) * 16 + (lane & 15);
        const int wofsC = half * 64 + sb;
        const int rX    = sb + 64 * (half * 2);
        const int rY    = rX + 64;
        // positional pair-blocks: own rows = {rX, rY}, other = partner's pair
        const int oOwnC = half ? 2048 : 0;
        const int oOthC = 2048 - oOwnC;

        const int btid = tid - 256;
        const int uB   = btid & 63;
        const int pad  = (uB >> 5) << 2;
        const int bB   = btid >> 6;           // 0 or 1
        float cB0 = 0.0f, cB1 = 0.0f, cB2 = 0.0f, cB3 = 0.0f;
        const bool hasJ3 = (NBT == 7) && (btid < 64);

        auto actL1 = [&](const float* g1a, int b, float& c) {
            int gi = b * NGATE + uB;
            float p0 = g1a[gi]       + g1b_s[gi];
            float p1 = g1a[gi + 64]  + g1b_s[gi + 64];
            float p2 = g1a[gi + 128] + g1b_s[gi + 128];
            float p3 = g1a[gi + 192] + g1b_s[gi + 192];
            float ii = sig_apx(p0), ff = sig_apx(p1), gv = tanh_apx(p2), oo = sig_apx(p3);
            c = ff * c + ii * gv;
            h1_s[b * HSTRIDE + uB + pad] = oo * tanh_apx(c);
        };

        for (int t = 0; t < T_STEPS; t++) {
            u64 aOwnX[NBT], aOwnY[NBT], aOthX[NBT], aOthY[NBT];
#pragma unroll
            for (int b = 0; b < NBT; b++) { aOwnX[b]=0ull; aOwnY[b]=0ull; aOthX[b]=0ull; aOthY[b]=0ull; }
#pragma unroll
            for (int kc = 0; kc < 8; kc++) {
                ulonglong2 wOwnX = wq[8192 + oOwnC        + kc * 128 + wofsC];
                ulonglong2 wOwnY = wq[8192 + oOwnC + 1024 + kc * 128 + wofsC];
                ulonglong2 wOthX = wq[8192 + oOthC        + kc * 128 + wofsC];
                ulonglong2 wOthY = wq[8192 + oOthC + 1024 + kc * 128 + wofsC];
#pragma unroll
                for (int b = 0; b < NBT; b++) {
                    ulonglong2 h2 = *(const ulonglong2*)(h1_s + b * HSTRIDE + hofs + kc * 4);
                    aOwnX[b] = ffma2(wOwnX.x, h2.x, aOwnX[b]); aOwnX[b] = ffma2(wOwnX.y, h2.y, aOwnX[b]);
                    aOwnY[b] = ffma2(wOwnY.x, h2.x, aOwnY[b]); aOwnY[b] = ffma2(wOwnY.y, h2.y, aOwnY[b]);
                    aOthX[b] = ffma2(wOthX.x, h2.x, aOthX[b]); aOthX[b] = ffma2(wOthX.y, h2.y, aOthX[b]);
                    aOthY[b] = ffma2(wOthY.x, h2.x, aOthY[b]); aOthY[b] = ffma2(wOthY.y, h2.y, aOthY[b]);
                }
            }
            // branchless single-shfl reduction
#pragma unroll
            for (int b = 0; b < NBT; b++) {
                float sendX = hadd2(aOthX[b]);
                float sendY = hadd2(aOthY[b]);
                float recvX = __shfl_xor_sync(0xffffffffu, sendX, 16);
                float recvY = __shfl_xor_sync(0xffffffffu, sendY, 16);
                g1b_s[b * NGATE + rX] = hadd2(aOwnX[b]) + recvX;
                g1b_s[b * NGATE + rY] = hadd2(aOwnY[b]) + recvY;
            }
            BAR_SYNC(6, 128);                 // g1b drained (beta-wide)
            BAR_SYNC(1 + (t & 1), 384);       // FULL: wait g1a(t) from alpha
            const float* g1a = g1a_s + (t & 1) * G1A_SLOT;

            actL1(g1a, bB,     cB0);          // act1(t)
            actL1(g1a, bB + 2, cB1);
            actL1(g1a, bB + 4, cB2);
            if (hasJ3) actL1(g1a, bB + 6, cB3);

            BAR_ARRIVE(3 + (t & 1), 384);     // EMPTY: g1a slot consumed
            BAR_SYNC(6, 128);                 // h1(t) visible for next mv
        }
    }
    __syncthreads();

    // ---- output FC ----
    if (tid < 2 * NBT) {
        int b = (tid < NBT) ? tid : tid - NBT;
        const float* hp = (tid < NBT) ? h0_s : h1_s;
        float s = b_fc[0];
#pragma unroll
        for (int uu = 0; uu < 64; uu++)
            s = fmaf(hp[b * HSTRIDE + uu + ((uu >> 5) << 2)], wfc_s[uu], s);
        out[(tid < NBT ? 0 : B_TOTAL) + bbase + b] = s;
    }
}

__global__ void __launch_bounds__(NTHREADS, 1)
lstm2_kernel(const float* __restrict__ x,
             const float* __restrict__ W_ih0, const float* __restrict__ W_hh0,
             const float* __restrict__ b_ih0, const float* __restrict__ b_hh0,
             const float* __restrict__ W_ih1, const float* __restrict__ W_hh1,
             const float* __restrict__ b_ih1, const float* __restrict__ b_hh1,
             const float* __restrict__ W_fc,  const float* __restrict__ b_fc,
             float* __restrict__ out)
{
    extern __shared__ char smem[];
    ulonglong2* wq = (ulonglong2*)(smem + SM_W);
    float* g0_s  = (float*)(smem + SM_G0);
    float* g1a_s = (float*)(smem + SM_G1A);
    float* g1b_s = (float*)(smem + SM_G1B);
    float* h0_s  = (float*)(smem + SM_H0);
    float* h1_s  = (float*)(smem + SM_H1);
    float* wfc_s = (float*)(smem + SM_WFC);

    const int tid = threadIdx.x;

    // ---- upload weights into conflict-free quad layouts ----
    for (int idx = tid; idx < 4096; idx += NTHREADS) {
        int row = idx >> 4, q = idx & 15;
        int hh = q >> 3, kc = q & 7;
        int dA = (row >> 7) * 2048 + kc * 256 + hh * 128 + (row & 127);
        wq[dA]        = ((const ulonglong2*)W_hh0)[idx];
        wq[4096 + dA] = ((const ulonglong2*)W_ih1)[idx];
        int dC = 8192 + (row >> 6) * 1024 + kc * 128 + hh * 64 + (row & 63);
        wq[dC] = ((const ulonglong2*)W_hh1)[idx];
    }
    if (tid < 64) wfc_s[tid] = W_fc[tid];

    if (blockIdx.x < NCTA7) {
        lstm_body<7>(blockIdx.x * 7, x, W_ih0, b_ih0, b_hh0, b_ih1, b_hh1,
                     b_fc, out, wq, g0_s, g1a_s, g1b_s, h0_s, h1_s, wfc_s);
    } else {
        lstm_body<6>(NCTA7 * 7 + (blockIdx.x - NCTA7) * 6, x, W_ih0, b_ih0, b_hh0,
                     b_ih1, b_hh1, b_fc, out, wq, g0_s, g1a_s, g1b_s, h0_s, h1_s, wfc_s);
    }
}

extern "C" void kernel_launch(void* const* d_in, const int* in_sizes, int n_in,
                              void* d_out, int out_size) {
    const float* x     = (const float*)d_in[0];
    const float* W_ih0 = (const float*)d_in[1];
    const float* W_hh0 = (const float*)d_in[2];
    const float* b_ih0 = (const float*)d_in[3];
    const float* b_hh0 = (const float*)d_in[4];
    const float* W_ih1 = (const float*)d_in[5];
    const float* W_hh1 = (const float*)d_in[6];
    const float* b_ih1 = (const float*)d_in[7];
    const float* b_hh1 = (const float*)d_in[8];
    const float* W_fc  = (const float*)d_in[9];
    const float* b_fc  = (const float*)d_in[10];
    float* out = (float*)d_out;

    cudaFuncSetAttribute(lstm2_kernel,
                         cudaFuncAttributeMaxDynamicSharedMemorySize, SMEM_BYTES);
    lstm2_kernel<<<NCTA, NTHREADS, SMEM_BYTES>>>(
        x, W_ih0, W_hh0, b_ih0, b_hh0,
        W_ih1, W_hh1, b_ih1, b_hh1, W_fc, b_fc, out);
}